// round 13
// baseline (speedup 1.0000x reference)
#include <cuda_runtime.h>
#include <math.h>
#include <stdint.h>

#define Bx   32
#define Sx   256
#define EMBD 300
#define HIDD 300
#define NTAG 9
#define GATES 1200          // 4*HIDD
#define NCOL  2400          // both directions

// ---------------- scratch (static device globals; no allocs) ----------------
__device__ float g_gx[19660800];              // (S,B,2400) input-transform + biases
__device__ float g_H [4915200];               // (S,B,600) hidden states (fwd|bwd)
__device__ float g_sc[Bx*Sx];                 // CRF numerator terms
__device__ float g_res[Bx];                   // per-batch llh terms
__device__ int   g_cf[64];                    // per-mblock fwd-col completion
__device__ int   g_cb[64];                    // per-mblock bwd-col completion

__device__ __forceinline__ float fsigm(float x){ return 1.f/(1.f+__expf(-x)); }
__device__ __forceinline__ float ftanh(float x){
    float ax=fabsf(x);
    float t=__expf(-2.f*ax);
    float r=(1.f-t)/(1.f+t);
    return copysignf(r,x);
}

// ---- packed fp32x2 helpers (sm_103a FFMA2 path) ----
__device__ __forceinline__ unsigned long long pk2(float lo, float hi){
    unsigned long long r;
    asm("mov.b64 %0, {%1,%2};" : "=l"(r) : "f"(lo), "f"(hi));
    return r;
}
__device__ __forceinline__ void ffma2(unsigned long long& d,
                                      unsigned long long a, unsigned long long b){
    asm("fma.rn.f32x2 %0, %1, %2, %0;" : "+l"(d) : "l"(a), "l"(b));
}

__device__ __forceinline__ uint32_t smem_u32(const void* p){
    uint32_t a;
    asm("{ .reg .u64 t; cvta.to.shared.u64 t, %1; cvt.u32.u64 %0, t; }"
        : "=r"(a) : "l"(p));
    return a;
}
__device__ __forceinline__ float4 dsmem_ld4(uint32_t local_addr, uint32_t rank){
    uint32_t ra; float4 v;
    asm volatile("mapa.shared::cluster.u32 %0, %1, %2;" : "=r"(ra) : "r"(local_addr), "r"(rank));
    asm volatile("ld.shared::cluster.v4.f32 {%0,%1,%2,%3}, [%4];"
        : "=f"(v.x),"=f"(v.y),"=f"(v.z),"=f"(v.w) : "r"(ra));
    return v;
}
__device__ __forceinline__ void mbar_arrive_peer(uint32_t mb_local, uint32_t rank){
    asm volatile(
        "{\n\t"
        ".reg .b32 ra;\n\t"
        "mapa.shared::cluster.u32 ra, %0, %1;\n\t"
        "mbarrier.arrive.shared::cluster.b64 _, [ra];\n\t"
        "}"
        :: "r"(mb_local), "r"(rank) : "memory");
}
__device__ __forceinline__ void mbar_wait_cluster(uint32_t mb, uint32_t parity){
    asm volatile(
        "{\n\t"
        ".reg .pred P;\n\t"
        "WL_%=:\n\t"
        "mbarrier.try_wait.parity.acquire.cluster.shared::cta.b64 P, [%0], %1, 0x989680;\n\t"
        "@P bra.uni WD_%=;\n\t"
        "bra.uni WL_%=;\n\t"
        "WD_%=:\n\t"
        "}"
        :: "r"(mb), "r"(parity) : "memory");
}
__device__ __forceinline__ int ld_acquire(const int* p){
    int v;
    asm volatile("ld.acquire.gpu.global.s32 %0, [%1];" : "=r"(v) : "l"(p) : "memory");
    return v;
}
__device__ __forceinline__ void red_release(int* p){
    asm volatile("red.release.gpu.global.add.s32 [%0], %1;" :: "l"(p), "r"(1) : "memory");
}

// ---------------- K0: counter reset ----------------
__global__ void k_init(){
    int t=threadIdx.x;
    if (t<64)      g_cf[t]=0;
    else if (t<128) g_cb[t-64]=0;
}

// ---------------- K1: fused embed + gx GEMM, JIT two-ended production --------
// Launched with a 176KB dummy dynamic-smem allocation so it can NEVER co-reside
// with a k_recur CTA (59KB) nor with another gx block: it runs 1-per-SM on the
// 52 SMs the recurrence doesn't occupy.
// grid 1280: even ids -> ascending (bm 0..63, nb 0..9, fwd cols),
// odd ids -> descending (bm 63..0, nb 9..18, bwd cols); nb=9 computed by both.
#define GX_DUMMY_SMEM 180224
__global__ void __launch_bounds__(256) k_gx(
        const int* __restrict__ x, const float* __restrict__ emb,
        const float* __restrict__ wf, const float* __restrict__ wb,
        const float* __restrict__ bif, const float* __restrict__ bhf,
        const float* __restrict__ bib, const float* __restrict__ bhb){
    __shared__ float As[8][132];
    __shared__ float Bs[8][128];
    int t  = threadIdx.x;
    int i  = blockIdx.x;
    int half = i>>1;
    int side, bm, nb;
    if ((i&1)==0){ side=0; bm=half/10;    nb=half%10;   }
    else         { side=1; bm=63-half/10; nb=9+half%10; }
    int m0 = bm*128;
    int n0 = nb*128;
    int tx = t & 15, ty = t >> 4;

    unsigned long long acc2[8][4];
    #pragma unroll
    for (int ii=0;ii<8;ii++)
        #pragma unroll
        for (int j=0;j<4;j++) acc2[ii][j]=pk2(0.f,0.f);

    int arow = t>>1, ahalf = t&1;
    int bn = t>>1,  bh = t&1;
    int m_ = m0 + arow;
    int s_ = m_ >> 5, b_ = m_ & 31;
    const float* arowp = emb + (size_t)__ldg(&x[b_*Sx + s_])*EMBD;

    bool brow_ok = (n0+bn) < NCOL;
    const float* wrp = brow_ok
        ? ((n0+bn) < GATES ? wf + (size_t)(n0+bn)*EMBD
                           : wb + (size_t)(n0+bn-GATES)*EMBD)
        : wf;

    float4 aR, bRv;
    {
        aR  = *(const float4*)(arowp + ahalf*4);
        bRv = brow_ok ? *(const float4*)(wrp + bh*4)
                      : make_float4(0.f,0.f,0.f,0.f);
    }
    for (int ck=0; ck<38; ck++){
        __syncthreads();
        {   float av[4]={aR.x,aR.y,aR.z,aR.w};
            float bv[4]={bRv.x,bRv.y,bRv.z,bRv.w};
            #pragma unroll
            for (int ii=0;ii<4;ii++){ As[ahalf*4+ii][arow]=av[ii]; Bs[bh*4+ii][bn]=bv[ii]; }
        }
        __syncthreads();
        if (ck < 37){
            int k0=(ck+1)*8;
            int ka = k0 + ahalf*4;
            int kb = k0 + bh*4;
            aR = (ka<EMBD) ? *(const float4*)(arowp + ka)
                           : make_float4(0.f,0.f,0.f,0.f);
            bRv = (brow_ok && kb<EMBD) ? *(const float4*)(wrp + kb)
                                       : make_float4(0.f,0.f,0.f,0.f);
        }
        #pragma unroll
        for (int kk=0;kk<8;kk++){
            float4 a0=*(const float4*)&As[kk][ty*8];
            float4 a1=*(const float4*)&As[kk][ty*8+4];
            float av[8]={a0.x,a0.y,a0.z,a0.w,a1.x,a1.y,a1.z,a1.w};
            unsigned long long ad[8];
            #pragma unroll
            for (int ii=0;ii<8;ii++) ad[ii]=pk2(av[ii],av[ii]);
            ulonglong2 bq0 = *(const ulonglong2*)&Bs[kk][tx*8];
            ulonglong2 bq1 = *(const ulonglong2*)&Bs[kk][tx*8+4];
            unsigned long long bp[4]={bq0.x,bq0.y,bq1.x,bq1.y};
            #pragma unroll
            for (int ii=0;ii<8;ii++)
                #pragma unroll
                for (int j=0;j<4;j++)
                    ffma2(acc2[ii][j], ad[ii], bp[j]);
        }
    }
    #pragma unroll
    for (int ii=0;ii<8;ii++){
        int gm = m0 + ty*8 + ii;
        float vv[8];
        #pragma unroll
        for (int j=0;j<4;j++){
            asm("mov.b64 {%0,%1}, %2;" : "=f"(vv[2*j]), "=f"(vv[2*j+1]) : "l"(acc2[ii][j]));
        }
        #pragma unroll
        for (int j0=0;j0<8;j0+=4){
            int gn = n0 + tx*8 + j0;
            if (gn < NCOL){
                float ww[4];
                #pragma unroll
                for (int j=0;j<4;j++){
                    int c=gn+j;
                    float bias = (c<GATES)? bif[c]+bhf[c] : bib[c-GATES]+bhb[c-GATES];
                    ww[j]=vv[j0+j]+bias;
                }
                *(float4*)(g_gx + (size_t)gm*NCOL + gn) =
                    make_float4(ww[0],ww[1],ww[2],ww[3]);
            }
        }
    }
    __syncthreads();
    if (t==0) red_release(side ? &g_cb[bm] : &g_cf[bm]);
}

// ---------------- K2: cluster-parallel persistent BiLSTM recurrence ----------
#define HSC   25        // hidden units per CTA
#define NHSC  12        // CTAs per cluster (hidden slices)
#define NBSC  4         // batch slices (8 each)
#define BCH   8         // batch per CTA
#define NGC   100       // 4*HSC gate rows per CTA
#define KSP   12        // k chunks
#define KCH   25        // k per chunk
#define PROWC 10        // padded Part row stride (even -> 8B-aligned pair stores)
#define HS2_OFF  0
#define HOUT_OFF 2400
#define PART_OFF 2800
#define CS_OFF   (PART_OFF + KSP*NGC*PROWC)
#define MB_OFF   (CS_OFF + 200)
#define RECUR_SMEM ((MB_OFF + 4)*4)

__global__ void __launch_bounds__(256,1) k_recur(
        const float* __restrict__ whhf, const float* __restrict__ whhb){
    extern __shared__ float sm[];
    float* Hs2  = sm + HS2_OFF;    // [300][8]  full h(s-1), k-major x batch
    float* Hout = sm + HOUT_OFF;   // [2][25*8] own h slice, double buffered
    float* Part = sm + PART_OFF;   // [12][100][10]
    float* Cs   = sm + CS_OFF;     // [25*8]

    int t = threadIdx.x;
    int cid  = blockIdx.x / NHSC;
    uint32_t rank = blockIdx.x % NHSC;
    int dir = cid >> 2;
    int bs  = cid & 3;
    int b0g = bs*BCH;
    int j0  = rank*HSC;
    const float* whh = dir ? whhb : whhf;
    const int* gxc = dir ? g_cb : g_cf;

    bool comp = (t < 240);
    int kp = t/20, gt = t%20;

    float W[5][25];
    if (comp){
        #pragma unroll
        for (int rr=0;rr<5;rr++){
            int lr = gt*5+rr;
            int type = lr/HSC, jj = lr - type*HSC;
            const float* src = whh + (size_t)(type*HIDD + j0 + jj)*HIDD + kp*KCH;
            #pragma unroll
            for (int k=0;k<KCH;k++) W[rr][k]=src[k];
        }
    }
    for (int i=t;i<2400;i+=256) Hs2[i]=0.f;
    for (int i=t;i<400;i+=256)  Hout[i]=0.f;
    for (int i=t;i<200;i+=256)  Cs[i]=0.f;

    uint32_t smb = smem_u32(sm);
    uint32_t mb  = smb + MB_OFF*4;
    if (t==0){
        asm volatile("mbarrier.init.shared.b64 [%0], %1;" :: "r"(mb), "r"(NHSC) : "memory");
    }
    __syncthreads();
    asm volatile("barrier.cluster.arrive.aligned;" ::: "memory");
    asm volatile("barrier.cluster.wait.aligned;"   ::: "memory");

    bool mycell = (t < 200);
    int cb = t/HSC, cj = t - cb*HSC;

    for (int step=0; step<Sx; step++){
        int s = dir ? (Sx-1-step) : step;
        int buf = step & 1;

        // wait until gx for this timestep's columns has been produced
        if (t==0){
            while (ld_acquire(&gxc[s>>2]) < 10) { }
        }

        if (step>0){
            mbar_wait_cluster(mb, (uint32_t)((step-1)&1));
            int pbuf = (step-1)&1;
            for (int i=t;i<600;i+=256){
                int k = i>>1, half = i&1;
                uint32_t peer = (uint32_t)(k/HSC);
                int koff = k - (int)peer*HSC;
                uint32_t la = smb + (uint32_t)((HOUT_OFF + pbuf*200 + koff*8 + half*4)*4);
                float4 v = dsmem_ld4(la, peer);
                ((float4*)Hs2)[i] = v;
            }
        }
        __syncthreads();                                    // A (Hs2 + gx visible)

        // gx loads issued here; latency hides under the GEMM below
        float pgi=0.f,pgf=0.f,pgg=0.f,pgo=0.f;
        if (mycell){
            const float* gp = g_gx + ((size_t)(s*Bx + b0g + cb))*NCOL + dir*GATES + (j0+cj);
            pgi=gp[0]; pgf=gp[HIDD]; pgg=gp[2*HIDD]; pgo=gp[3*HIDD];
        }

        // recurrent GEMM: 5 rows x 4 batch-pairs x 25 k per thread (f32x2)
        if (comp){
            unsigned long long acc[5][4];
            #pragma unroll
            for (int rr=0;rr<5;rr++)
                #pragma unroll
                for (int p=0;p<4;p++) acc[rr][p]=pk2(0.f,0.f);
            const float* hbase = Hs2 + (kp*KCH)*8;
            #pragma unroll
            for (int c=0;c<KCH;c++){
                ulonglong2 hA = *(const ulonglong2*)(hbase + c*8);
                ulonglong2 hB = *(const ulonglong2*)(hbase + c*8 + 4);
                unsigned long long hp[4]={hA.x,hA.y,hB.x,hB.y};
                #pragma unroll
                for (int rr=0;rr<5;rr++){
                    unsigned long long wd = pk2(W[rr][c],W[rr][c]);
                    #pragma unroll
                    for (int p=0;p<4;p++) ffma2(acc[rr][p], wd, hp[p]);
                }
            }
            #pragma unroll
            for (int rr=0;rr<5;rr++){
                int row = gt*5+rr;
                #pragma unroll
                for (int p=0;p<4;p++)
                    *(unsigned long long*)&Part[(kp*NGC+row)*PROWC + 2*p] = acc[rr][p];
            }
        }
        __syncthreads();                                    // B

        if (mycell){
            float gi=pgi, gf=pgf, gg=pgg, go=pgo;
            #pragma unroll
            for (int kq=0;kq<KSP;kq++){
                gi += Part[(kq*NGC + 0*HSC+cj)*PROWC + cb];
                gf += Part[(kq*NGC + 1*HSC+cj)*PROWC + cb];
                gg += Part[(kq*NGC + 2*HSC+cj)*PROWC + cb];
                go += Part[(kq*NGC + 3*HSC+cj)*PROWC + cb];
            }
            float co=Cs[cj*8+cb];
            float cn=fsigm(gf)*co + fsigm(gi)*ftanh(gg);
            float hn=fsigm(go)*ftanh(cn);
            Cs[cj*8+cb]=cn;
            Hout[buf*200 + cj*8 + cb]=hn;
            g_H[((size_t)(s*Bx + b0g + cb))*(2*HIDD) + dir*HIDD + j0 + cj]=hn;
        }
        __syncthreads();                                    // C (Hout published)
        if (t < NHSC) mbar_arrive_peer(mb, (uint32_t)t);
    }
    asm volatile("barrier.cluster.arrive.aligned;" ::: "memory");
    asm volatile("barrier.cluster.wait.aligned;"   ::: "memory");
}

// ---------------- K3a: logits + softmax + CRF numerator terms ----------------
__global__ void __launch_bounds__(288) k_head(
        const float* __restrict__ linw, const float* __restrict__ linb,
        const int* __restrict__ y, const float* __restrict__ start_t,
        const float* __restrict__ end_t, const float* __restrict__ trans,
        float* __restrict__ out){
    __shared__ float sh[2*HIDD];
    __shared__ float lg[NTAG];
    int bxid=blockIdx.x;
    int b=bxid/Sx, s=bxid%Sx;
    int t=threadIdx.x;
    const float* hrow=g_H + (size_t)(s*Bx+b)*(2*HIDD);
    for (int k=t;k<2*HIDD;k+=288) sh[k]=hrow[k];
    __syncthreads();
    int w=t>>5, lane=t&31;
    float acc=0.f;
    for (int k=lane;k<2*HIDD;k+=32) acc=fmaf(sh[k],__ldg(&linw[w*(2*HIDD)+k]),acc);
    #pragma unroll
    for (int off=16;off;off>>=1) acc += __shfl_down_sync(0xffffffffu,acc,off);
    if (lane==0) lg[w]=acc+__ldg(&linb[w]);
    __syncthreads();
    if (t==0){
        float m=lg[0];
        #pragma unroll
        for (int i=1;i<NTAG;i++) m=fmaxf(m,lg[i]);
        float e[NTAG]; float ssum=0.f;
        #pragma unroll
        for (int i=0;i<NTAG;i++){ e[i]=expf(lg[i]-m); ssum+=e[i]; }
        float inv=1.f/ssum;
        float* po=out + ((size_t)b*Sx + s)*NTAG;
        float pr[NTAG];
        #pragma unroll
        for (int i=0;i<NTAG;i++){ pr[i]=e[i]*inv; po[i]=pr[i]; }
        int yc=__ldg(&y[b*Sx+s]);
        float term=pr[yc];
        if (s==0) term += __ldg(&start_t[yc]);
        else      term += __ldg(&trans[__ldg(&y[b*Sx+s-1])*NTAG + yc]);
        if (s==Sx-1) term += __ldg(&end_t[yc]);
        g_sc[b*Sx+s]=term;
    }
}

// ---------------- K3b: CRF forward, linear domain + smem-staged emissions ----
__global__ void __launch_bounds__(32) k_crf(
        const float* __restrict__ start_t, const float* __restrict__ end_t,
        const float* __restrict__ trans, const float* __restrict__ out){
    __shared__ float sp[Sx*NTAG];
    __shared__ float ssc[Sx];
    int w = blockIdx.x;
    int lane = threadIdx.x;

    {
        const float4* src = (const float4*)(out + (size_t)w*Sx*NTAG);
        for (int i=lane;i<(Sx*NTAG)/4;i+=32) ((float4*)sp)[i]=src[i];
        const float4* ssrc = (const float4*)(g_sc + w*Sx);
        for (int i=lane;i<Sx/4;i+=32) ((float4*)ssc)[i]=ssrc[i];
    }
    __syncwarp();

    int j = (lane<NTAG)? lane : 0;
    float M[NTAG];
    #pragma unroll
    for (int i=0;i<NTAG;i++) M[i]=__expf(__ldg(&trans[i*NTAG+j]));

    float A = __expf(__ldg(&start_t[j]) + sp[j]);
    float off = 0.f;
    for (int s=1;s<Sx;s++){
        float em = sp[s*NTAG+j];
        float a[NTAG];
        #pragma unroll
        for (int i=0;i<NTAG;i++) a[i]=__shfl_sync(0xffffffffu, A, i);
        float S0=0.f, S1=0.f, S2=0.f;
        #pragma unroll
        for (int i=0;i<NTAG;i+=3){
            S0=fmaf(M[i  ],a[i  ],S0);
            S1=fmaf(M[i+1],a[i+1],S1);
            S2=fmaf(M[i+2],a[i+2],S2);
        }
        A = (S0+S1+S2) * __expf(em);
        if ((s&15)==0){
            float tot=0.f;
            #pragma unroll
            for (int i=0;i<NTAG;i++) tot += __shfl_sync(0xffffffffu, A, i);
            A = A / tot;
            off += __logf(tot);
        }
    }
    float v = A * __expf(__ldg(&end_t[j]));
    float dl=0.f;
    #pragma unroll
    for (int i=0;i<NTAG;i++) dl += __shfl_sync(0xffffffffu, v, i);
    float denom = __logf(dl) + off;
    float sc=0.f;
    for (int s=lane;s<Sx;s+=32) sc+=ssc[s];
    #pragma unroll
    for (int o=16;o;o>>=1) sc += __shfl_down_sync(0xffffffffu,sc,o);
    if (lane==0) g_res[w]=sc-denom;
}

// ---------------- K3c: final deterministic loss sum ----------------
__global__ void __launch_bounds__(32) k_loss(float* __restrict__ out){
    if (threadIdx.x==0){
        float llh=0.f;
        #pragma unroll
        for (int bb=0;bb<Bx;bb++) llh+=g_res[bb];
        out[(size_t)Bx*Sx*NTAG]=-llh;
    }
}

// ---------------- launcher ----------------
extern "C" void kernel_launch(void* const* d_in, const int* in_sizes, int n_in,
                              void* d_out, int out_size){
    const int*   x     =(const int*)  d_in[0];
    const int*   y     =(const int*)  d_in[1];
    const float* emb   =(const float*)d_in[2];
    const float* wihf  =(const float*)d_in[3];
    const float* whhf  =(const float*)d_in[4];
    const float* bihf  =(const float*)d_in[5];
    const float* bhhf  =(const float*)d_in[6];
    const float* wihb  =(const float*)d_in[7];
    const float* whhb  =(const float*)d_in[8];
    const float* bihb  =(const float*)d_in[9];
    const float* bhhb  =(const float*)d_in[10];
    const float* linw  =(const float*)d_in[11];
    const float* linb  =(const float*)d_in[12];
    const float* startt=(const float*)d_in[13];
    const float* endt  =(const float*)d_in[14];
    const float* trans =(const float*)d_in[15];
    float* out=(float*)d_out;
    (void)in_sizes; (void)n_in; (void)out_size;

    static int once = 0;
    static cudaStream_t s2;
    static cudaEvent_t evI, evG;
    if (!once){
        cudaFuncSetAttribute(k_recur, cudaFuncAttributeMaxDynamicSharedMemorySize, RECUR_SMEM);
        cudaFuncSetAttribute(k_recur, cudaFuncAttributeNonPortableClusterSizeAllowed, 1);
        cudaFuncSetAttribute(k_gx, cudaFuncAttributeMaxDynamicSharedMemorySize, GX_DUMMY_SMEM);
        cudaStreamCreateWithFlags(&s2, cudaStreamNonBlocking);
        cudaEventCreateWithFlags(&evI, cudaEventDisableTiming);
        cudaEventCreateWithFlags(&evG, cudaEventDisableTiming);
        once = 1;
    }

    // counters reset; then recur launches FIRST (claims its 96 SMs), gx fills
    // the remaining 52 SMs (1 block/SM via the smem wall) concurrently.
    k_init<<<1,128>>>();
    cudaEventRecord(evI, 0);
    cudaStreamWaitEvent(s2, evI, 0);

    cudaLaunchConfig_t cfg = {};
    cfg.gridDim = dim3(2*NBSC*NHSC, 1, 1);   // 96 CTAs = 8 clusters x 12
    cfg.blockDim = dim3(256, 1, 1);
    cfg.dynamicSmemBytes = RECUR_SMEM;
    cfg.stream = 0;
    cudaLaunchAttribute attrs[1];
    attrs[0].id = cudaLaunchAttributeClusterDimension;
    attrs[0].val.clusterDim.x = NHSC;
    attrs[0].val.clusterDim.y = 1;
    attrs[0].val.clusterDim.z = 1;
    cfg.attrs = attrs;
    cfg.numAttrs = 1;
    cudaLaunchKernelEx(&cfg, k_recur, whhf, whhb);

    k_gx<<<1280,256,GX_DUMMY_SMEM,s2>>>(x, emb, wihf, wihb, bihf, bhhf, bihb, bhhb);
    cudaEventRecord(evG, s2);

    // join: tail kernels need recur (stream order) AND gx (event)
    cudaStreamWaitEvent(0, evG, 0);
    k_head<<<Bx*Sx,288>>>(linw, linb, y, startt, endt, trans, out);
    k_crf<<<Bx,32>>>(startt, endt, trans, out);
    k_loss<<<1,32>>>(out);
}

// round 14
// speedup vs baseline: 1.0357x; 1.0357x over previous
#include <cuda_runtime.h>
#include <math.h>
#include <stdint.h>

#define Bx   32
#define Sx   256
#define EMBD 300
#define HIDD 300
#define NTAG 9
#define GATES 1200          // 4*HIDD
#define NCOL  2400          // both directions

// ---------------- scratch (static device globals; no allocs) ----------------
__device__ float g_gx[19660800];              // (S,B,2400) input-transform + biases
__device__ float g_H [4915200];               // (S,B,600) hidden states (fwd|bwd)
__device__ float g_sc[Bx*Sx];                 // CRF numerator terms
__device__ float g_res[Bx];                   // per-batch llh terms

__device__ __forceinline__ float fsigm(float x){ return 1.f/(1.f+__expf(-x)); }
__device__ __forceinline__ float ftanh(float x){
    float ax=fabsf(x);
    float t=__expf(-2.f*ax);
    float r=(1.f-t)/(1.f+t);
    return copysignf(r,x);
}

// ---- packed fp32x2 helpers (sm_103a FFMA2 path) ----
__device__ __forceinline__ unsigned long long pk2(float lo, float hi){
    unsigned long long r;
    asm("mov.b64 %0, {%1,%2};" : "=l"(r) : "f"(lo), "f"(hi));
    return r;
}
__device__ __forceinline__ void ffma2(unsigned long long& d,
                                      unsigned long long a, unsigned long long b){
    asm("fma.rn.f32x2 %0, %1, %2, %0;" : "+l"(d) : "l"(a), "l"(b));
}

__device__ __forceinline__ uint32_t smem_u32(const void* p){
    uint32_t a;
    asm("{ .reg .u64 t; cvta.to.shared.u64 t, %1; cvt.u32.u64 %0, t; }"
        : "=r"(a) : "l"(p));
    return a;
}
__device__ __forceinline__ float4 dsmem_ld4(uint32_t local_addr, uint32_t rank){
    uint32_t ra; float4 v;
    asm volatile("mapa.shared::cluster.u32 %0, %1, %2;" : "=r"(ra) : "r"(local_addr), "r"(rank));
    asm volatile("ld.shared::cluster.v4.f32 {%0,%1,%2,%3}, [%4];"
        : "=f"(v.x),"=f"(v.y),"=f"(v.z),"=f"(v.w) : "r"(ra));
    return v;
}
__device__ __forceinline__ void mbar_arrive_peer(uint32_t mb_local, uint32_t rank){
    asm volatile(
        "{\n\t"
        ".reg .b32 ra;\n\t"
        "mapa.shared::cluster.u32 ra, %0, %1;\n\t"
        "mbarrier.arrive.shared::cluster.b64 _, [ra];\n\t"
        "}"
        :: "r"(mb_local), "r"(rank) : "memory");
}
__device__ __forceinline__ void mbar_wait_cluster(uint32_t mb, uint32_t parity){
    asm volatile(
        "{\n\t"
        ".reg .pred P;\n\t"
        "WL_%=:\n\t"
        "mbarrier.try_wait.parity.acquire.cluster.shared::cta.b64 P, [%0], %1, 0x989680;\n\t"
        "@P bra.uni WD_%=;\n\t"
        "bra.uni WL_%=;\n\t"
        "WD_%=:\n\t"
        "}"
        :: "r"(mb), "r"(parity) : "memory");
}

// ---------------- K1: fused embed + gx GEMM (8192 x 2400 x 300) --------------
__global__ void __launch_bounds__(256) k_gx(
        const int* __restrict__ x, const float* __restrict__ emb,
        const float* __restrict__ wf, const float* __restrict__ wb,
        const float* __restrict__ bif, const float* __restrict__ bhf,
        const float* __restrict__ bib, const float* __restrict__ bhb){
    __shared__ float As[8][132];
    __shared__ float Bs[8][128];
    int t  = threadIdx.x;
    int m0 = blockIdx.x*128;
    int n0 = blockIdx.y*128;
    int tx = t & 15, ty = t >> 4;

    unsigned long long acc2[8][4];
    #pragma unroll
    for (int i=0;i<8;i++)
        #pragma unroll
        for (int j=0;j<4;j++) acc2[i][j]=pk2(0.f,0.f);

    int arow = t>>1, ahalf = t&1;
    int bn = t>>1,  bh = t&1;
    int m_ = m0 + arow;
    int s_ = m_ >> 5, b_ = m_ & 31;
    const float* arowp = emb + (size_t)__ldg(&x[b_*Sx + s_])*EMBD;

    bool brow_ok = (n0+bn) < NCOL;
    const float* wrp = brow_ok
        ? ((n0+bn) < GATES ? wf + (size_t)(n0+bn)*EMBD
                           : wb + (size_t)(n0+bn-GATES)*EMBD)
        : wf;

    float4 aR, bRv;
    {
        aR  = *(const float4*)(arowp + ahalf*4);
        bRv = brow_ok ? *(const float4*)(wrp + bh*4)
                      : make_float4(0.f,0.f,0.f,0.f);
    }
    for (int ck=0; ck<38; ck++){
        __syncthreads();
        {   float av[4]={aR.x,aR.y,aR.z,aR.w};
            float bv[4]={bRv.x,bRv.y,bRv.z,bRv.w};
            #pragma unroll
            for (int i=0;i<4;i++){ As[ahalf*4+i][arow]=av[i]; Bs[bh*4+i][bn]=bv[i]; }
        }
        __syncthreads();
        if (ck < 37){
            int k0=(ck+1)*8;
            int ka = k0 + ahalf*4;
            int kb = k0 + bh*4;
            aR = (ka<EMBD) ? *(const float4*)(arowp + ka)
                           : make_float4(0.f,0.f,0.f,0.f);
            bRv = (brow_ok && kb<EMBD) ? *(const float4*)(wrp + kb)
                                       : make_float4(0.f,0.f,0.f,0.f);
        }
        #pragma unroll
        for (int kk=0;kk<8;kk++){
            float4 a0=*(const float4*)&As[kk][ty*8];
            float4 a1=*(const float4*)&As[kk][ty*8+4];
            float av[8]={a0.x,a0.y,a0.z,a0.w,a1.x,a1.y,a1.z,a1.w};
            unsigned long long ad[8];
            #pragma unroll
            for (int i=0;i<8;i++) ad[i]=pk2(av[i],av[i]);
            ulonglong2 bq0 = *(const ulonglong2*)&Bs[kk][tx*8];
            ulonglong2 bq1 = *(const ulonglong2*)&Bs[kk][tx*8+4];
            unsigned long long bp[4]={bq0.x,bq0.y,bq1.x,bq1.y};
            #pragma unroll
            for (int i=0;i<8;i++)
                #pragma unroll
                for (int j=0;j<4;j++)
                    ffma2(acc2[i][j], ad[i], bp[j]);
        }
    }
    #pragma unroll
    for (int i=0;i<8;i++){
        int gm = m0 + ty*8 + i;
        float vv[8];
        #pragma unroll
        for (int j=0;j<4;j++){
            asm("mov.b64 {%0,%1}, %2;" : "=f"(vv[2*j]), "=f"(vv[2*j+1]) : "l"(acc2[i][j]));
        }
        #pragma unroll
        for (int j0=0;j0<8;j0+=4){
            int gn = n0 + tx*8 + j0;
            if (gn < NCOL){
                float ww[4];
                #pragma unroll
                for (int j=0;j<4;j++){
                    int c=gn+j;
                    float bias = (c<GATES)? bif[c]+bhf[c] : bib[c-GATES]+bhb[c-GATES];
                    ww[j]=vv[j0+j]+bias;
                }
                *(float4*)(g_gx + (size_t)gm*NCOL + gn) =
                    make_float4(ww[0],ww[1],ww[2],ww[3]);
            }
        }
    }
}

// ---------------- K2: cluster-parallel persistent BiLSTM recurrence ----------
// R11 base + (a) one-step-ahead gx prefetch, (b) conflict-free Part layout
// Part2[kq][cb][row]: consumer lane stride 1 float (no conflicts); producer
// lane stride 5 floats (5 coprime 32 -> no conflicts).
#define HSC   25        // hidden units per CTA
#define NHSC  12        // CTAs per cluster (hidden slices)
#define NBSC  4         // batch slices (8 each)
#define BCH   8         // batch per CTA
#define NGC   100       // 4*HSC gate rows per CTA
#define KSP   12        // k chunks
#define KCH   25        // k per chunk
#define PR2   104       // padded row-plane stride (100 rows + 4 pad)
#define HS2_OFF  0
#define HOUT_OFF 2400
#define PART_OFF 2800
#define CS_OFF   (PART_OFF + KSP*BCH*PR2)
#define MB_OFF   (CS_OFF + 200)
#define RECUR_SMEM ((MB_OFF + 4)*4)

__global__ void __launch_bounds__(256,1) k_recur(
        const float* __restrict__ whhf, const float* __restrict__ whhb){
    extern __shared__ float sm[];
    float* Hs2  = sm + HS2_OFF;    // [300][8]  full h(s-1), k-major x batch
    float* Hout = sm + HOUT_OFF;   // [2][25*8] own h slice, double buffered
    float* Part = sm + PART_OFF;   // [12][8][104]  (kq, cb, row)
    float* Cs   = sm + CS_OFF;     // [25*8]

    int t = threadIdx.x;
    int cid  = blockIdx.x / NHSC;
    uint32_t rank = blockIdx.x % NHSC;
    int dir = cid >> 2;
    int bs  = cid & 3;
    int b0g = bs*BCH;
    int j0  = rank*HSC;
    const float* whh = dir ? whhb : whhf;

    bool comp = (t < 240);
    int kp = t/20, gt = t%20;

    float W[5][25];
    if (comp){
        #pragma unroll
        for (int rr=0;rr<5;rr++){
            int lr = gt*5+rr;
            int type = lr/HSC, jj = lr - type*HSC;
            const float* src = whh + (size_t)(type*HIDD + j0 + jj)*HIDD + kp*KCH;
            #pragma unroll
            for (int k=0;k<KCH;k++) W[rr][k]=src[k];
        }
    }
    for (int i=t;i<2400;i+=256) Hs2[i]=0.f;
    for (int i=t;i<400;i+=256)  Hout[i]=0.f;
    for (int i=t;i<200;i+=256)  Cs[i]=0.f;

    uint32_t smb = smem_u32(sm);
    uint32_t mb  = smb + MB_OFF*4;
    if (t==0){
        asm volatile("mbarrier.init.shared.b64 [%0], %1;" :: "r"(mb), "r"(NHSC) : "memory");
    }
    __syncthreads();
    asm volatile("barrier.cluster.arrive.aligned;" ::: "memory");
    asm volatile("barrier.cluster.wait.aligned;"   ::: "memory");

    bool mycell = (t < 200);
    int cb = t/HSC, cj = t - cb*HSC;

    // preload step-0 gx
    float pgi=0.f,pgf=0.f,pgg=0.f,pgo=0.f;
    if (mycell){
        int s0 = dir ? (Sx-1) : 0;
        const float* gp = g_gx + ((size_t)(s0*Bx + b0g + cb))*NCOL + dir*GATES + (j0+cj);
        pgi=gp[0]; pgf=gp[HIDD]; pgg=gp[2*HIDD]; pgo=gp[3*HIDD];
    }

    for (int step=0; step<Sx; step++){
        int buf = step & 1;

        if (step>0){
            mbar_wait_cluster(mb, (uint32_t)((step-1)&1));
            int pbuf = (step-1)&1;
            for (int i=t;i<600;i+=256){
                int k = i>>1, half = i&1;
                uint32_t peer = (uint32_t)(k/HSC);
                int koff = k - (int)peer*HSC;
                uint32_t la = smb + (uint32_t)((HOUT_OFF + pbuf*200 + koff*8 + half*4)*4);
                float4 v = dsmem_ld4(la, peer);
                ((float4*)Hs2)[i] = v;
            }
        }
        __syncthreads();                                    // A

        // prefetch NEXT step's gx; latency hides under the GEMM below
        float ngi=0.f,ngf=0.f,ngg=0.f,ngo=0.f;
        if (mycell && step+1<Sx){
            int sn = dir ? (Sx-2-step) : (step+1);
            const float* gp = g_gx + ((size_t)(sn*Bx + b0g + cb))*NCOL + dir*GATES + (j0+cj);
            ngi=gp[0]; ngf=gp[HIDD]; ngg=gp[2*HIDD]; ngo=gp[3*HIDD];
        }

        // recurrent GEMM: 5 rows x 4 batch-pairs x 25 k per thread (f32x2)
        if (comp){
            unsigned long long acc[5][4];
            #pragma unroll
            for (int rr=0;rr<5;rr++)
                #pragma unroll
                for (int p=0;p<4;p++) acc[rr][p]=pk2(0.f,0.f);
            const float* hbase = Hs2 + (kp*KCH)*8;
            #pragma unroll
            for (int c=0;c<KCH;c++){
                ulonglong2 hA = *(const ulonglong2*)(hbase + c*8);
                ulonglong2 hB = *(const ulonglong2*)(hbase + c*8 + 4);
                unsigned long long hp[4]={hA.x,hA.y,hB.x,hB.y};
                #pragma unroll
                for (int rr=0;rr<5;rr++){
                    unsigned long long wd = pk2(W[rr][c],W[rr][c]);
                    #pragma unroll
                    for (int p=0;p<4;p++) ffma2(acc[rr][p], wd, hp[p]);
                }
            }
            #pragma unroll
            for (int rr=0;rr<5;rr++){
                int row = gt*5+rr;
                #pragma unroll
                for (int p=0;p<4;p++){
                    float lo,hi;
                    asm("mov.b64 {%0,%1}, %2;" : "=f"(lo), "=f"(hi) : "l"(acc[rr][p]));
                    Part[(kp*BCH + 2*p  )*PR2 + row]=lo;
                    Part[(kp*BCH + 2*p+1)*PR2 + row]=hi;
                }
            }
        }
        __syncthreads();                                    // B

        if (mycell){
            int s = dir ? (Sx-1-step) : step;
            float gi=pgi, gf=pgf, gg=pgg, go=pgo;
            #pragma unroll
            for (int kq=0;kq<KSP;kq++){
                const float* pb = Part + (kq*BCH + cb)*PR2;
                gi += pb[0*HSC+cj];
                gf += pb[1*HSC+cj];
                gg += pb[2*HSC+cj];
                go += pb[3*HSC+cj];
            }
            float co=Cs[cj*8+cb];
            float cn=fsigm(gf)*co + fsigm(gi)*ftanh(gg);
            float hn=fsigm(go)*ftanh(cn);
            Cs[cj*8+cb]=cn;
            Hout[buf*200 + cj*8 + cb]=hn;
            g_H[((size_t)(s*Bx + b0g + cb))*(2*HIDD) + dir*HIDD + j0 + cj]=hn;
        }
        pgi=ngi; pgf=ngf; pgg=ngg; pgo=ngo;
        __syncthreads();                                    // C (Hout published)
        if (t < NHSC) mbar_arrive_peer(mb, (uint32_t)t);
    }
    asm volatile("barrier.cluster.arrive.aligned;" ::: "memory");
    asm volatile("barrier.cluster.wait.aligned;"   ::: "memory");
}

// ---------------- K3a: logits + softmax + CRF numerator terms ----------------
__global__ void __launch_bounds__(288) k_head(
        const float* __restrict__ linw, const float* __restrict__ linb,
        const int* __restrict__ y, const float* __restrict__ start_t,
        const float* __restrict__ end_t, const float* __restrict__ trans,
        float* __restrict__ out){
    __shared__ float sh[2*HIDD];
    __shared__ float lg[NTAG];
    int bxid=blockIdx.x;
    int b=bxid/Sx, s=bxid%Sx;
    int t=threadIdx.x;
    const float* hrow=g_H + (size_t)(s*Bx+b)*(2*HIDD);
    for (int k=t;k<2*HIDD;k+=288) sh[k]=hrow[k];
    __syncthreads();
    int w=t>>5, lane=t&31;
    float acc=0.f;
    for (int k=lane;k<2*HIDD;k+=32) acc=fmaf(sh[k],__ldg(&linw[w*(2*HIDD)+k]),acc);
    #pragma unroll
    for (int off=16;off;off>>=1) acc += __shfl_down_sync(0xffffffffu,acc,off);
    if (lane==0) lg[w]=acc+__ldg(&linb[w]);
    __syncthreads();
    if (t==0){
        float m=lg[0];
        #pragma unroll
        for (int i=1;i<NTAG;i++) m=fmaxf(m,lg[i]);
        float e[NTAG]; float ssum=0.f;
        #pragma unroll
        for (int i=0;i<NTAG;i++){ e[i]=expf(lg[i]-m); ssum+=e[i]; }
        float inv=1.f/ssum;
        float* po=out + ((size_t)b*Sx + s)*NTAG;
        float pr[NTAG];
        #pragma unroll
        for (int i=0;i<NTAG;i++){ pr[i]=e[i]*inv; po[i]=pr[i]; }
        int yc=__ldg(&y[b*Sx+s]);
        float term=pr[yc];
        if (s==0) term += __ldg(&start_t[yc]);
        else      term += __ldg(&trans[__ldg(&y[b*Sx+s-1])*NTAG + yc]);
        if (s==Sx-1) term += __ldg(&end_t[yc]);
        g_sc[b*Sx+s]=term;
    }
}

// ---------------- K3b: CRF forward, linear domain + smem-staged emissions ----
__global__ void __launch_bounds__(32) k_crf(
        const float* __restrict__ start_t, const float* __restrict__ end_t,
        const float* __restrict__ trans, const float* __restrict__ out){
    __shared__ float sp[Sx*NTAG];
    __shared__ float ssc[Sx];
    int w = blockIdx.x;
    int lane = threadIdx.x;

    {
        const float4* src = (const float4*)(out + (size_t)w*Sx*NTAG);
        for (int i=lane;i<(Sx*NTAG)/4;i+=32) ((float4*)sp)[i]=src[i];
        const float4* ssrc = (const float4*)(g_sc + w*Sx);
        for (int i=lane;i<Sx/4;i+=32) ((float4*)ssc)[i]=ssrc[i];
    }
    __syncwarp();

    int j = (lane<NTAG)? lane : 0;
    float M[NTAG];
    #pragma unroll
    for (int i=0;i<NTAG;i++) M[i]=__expf(__ldg(&trans[i*NTAG+j]));

    float A = __expf(__ldg(&start_t[j]) + sp[j]);
    float off = 0.f;
    for (int s=1;s<Sx;s++){
        float em = sp[s*NTAG+j];
        float a[NTAG];
        #pragma unroll
        for (int i=0;i<NTAG;i++) a[i]=__shfl_sync(0xffffffffu, A, i);
        float S0=0.f, S1=0.f, S2=0.f;
        #pragma unroll
        for (int i=0;i<NTAG;i+=3){
            S0=fmaf(M[i  ],a[i  ],S0);
            S1=fmaf(M[i+1],a[i+1],S1);
            S2=fmaf(M[i+2],a[i+2],S2);
        }
        A = (S0+S1+S2) * __expf(em);
        if ((s&15)==0){
            float tot=0.f;
            #pragma unroll
            for (int i=0;i<NTAG;i++) tot += __shfl_sync(0xffffffffu, A, i);
            A = A / tot;
            off += __logf(tot);
        }
    }
    float v = A * __expf(__ldg(&end_t[j]));
    float dl=0.f;
    #pragma unroll
    for (int i=0;i<NTAG;i++) dl += __shfl_sync(0xffffffffu, v, i);
    float denom = __logf(dl) + off;
    float sc=0.f;
    for (int s=lane;s<Sx;s+=32) sc+=ssc[s];
    #pragma unroll
    for (int o=16;o;o>>=1) sc += __shfl_down_sync(0xffffffffu,sc,o);
    if (lane==0) g_res[w]=sc-denom;
}

// ---------------- K3c: final deterministic loss sum ----------------
__global__ void __launch_bounds__(32) k_loss(float* __restrict__ out){
    if (threadIdx.x==0){
        float llh=0.f;
        #pragma unroll
        for (int bb=0;bb<Bx;bb++) llh+=g_res[bb];
        out[(size_t)Bx*Sx*NTAG]=-llh;
    }
}

// ---------------- launcher ----------------
extern "C" void kernel_launch(void* const* d_in, const int* in_sizes, int n_in,
                              void* d_out, int out_size){
    const int*   x     =(const int*)  d_in[0];
    const int*   y     =(const int*)  d_in[1];
    const float* emb   =(const float*)d_in[2];
    const float* wihf  =(const float*)d_in[3];
    const float* whhf  =(const float*)d_in[4];
    const float* bihf  =(const float*)d_in[5];
    const float* bhhf  =(const float*)d_in[6];
    const float* wihb  =(const float*)d_in[7];
    const float* whhb  =(const float*)d_in[8];
    const float* bihb  =(const float*)d_in[9];
    const float* bhhb  =(const float*)d_in[10];
    const float* linw  =(const float*)d_in[11];
    const float* linb  =(const float*)d_in[12];
    const float* startt=(const float*)d_in[13];
    const float* endt  =(const float*)d_in[14];
    const float* trans =(const float*)d_in[15];
    float* out=(float*)d_out;
    (void)in_sizes; (void)n_in; (void)out_size;

    static int once = 0;
    if (!once){
        cudaFuncSetAttribute(k_recur, cudaFuncAttributeMaxDynamicSharedMemorySize, RECUR_SMEM);
        cudaFuncSetAttribute(k_recur, cudaFuncAttributeNonPortableClusterSizeAllowed, 1);
        once = 1;
    }

    dim3 gg(8192/128, (NCOL+127)/128);
    k_gx<<<gg,256>>>(x, emb, wihf, wihb, bihf, bhhf, bihb, bhhb);

    cudaLaunchConfig_t cfg = {};
    cfg.gridDim = dim3(2*NBSC*NHSC, 1, 1);   // 96 CTAs = 8 clusters x 12
    cfg.blockDim = dim3(256, 1, 1);
    cfg.dynamicSmemBytes = RECUR_SMEM;
    cfg.stream = 0;
    cudaLaunchAttribute attrs[1];
    attrs[0].id = cudaLaunchAttributeClusterDimension;
    attrs[0].val.clusterDim.x = NHSC;
    attrs[0].val.clusterDim.y = 1;
    attrs[0].val.clusterDim.z = 1;
    cfg.attrs = attrs;
    cfg.numAttrs = 1;
    cudaLaunchKernelEx(&cfg, k_recur, whhf, whhb);

    k_head<<<Bx*Sx,288>>>(linw, linb, y, startt, endt, trans, out);
    k_crf<<<Bx,32>>>(startt, endt, trans, out);
    k_loss<<<1,32>>>(out);
}

// round 15
// speedup vs baseline: 1.2865x; 1.2422x over previous
#include <cuda_runtime.h>
#include <math.h>
#include <stdint.h>

#define Bx   32
#define Sx   256
#define EMBD 300
#define HIDD 300
#define NTAG 9
#define GATES 1200          // 4*HIDD
#define NCOL  2400          // both directions

// ---------------- scratch (static device globals; no allocs) ----------------
__device__ float g_gx[19660800];              // (S,B,2400) input-transform + biases
__device__ float g_H [4915200];               // (S,B,600) hidden states (fwd|bwd)
__device__ float g_sc[Bx*Sx];                 // CRF numerator terms
__device__ float g_res[Bx];                   // per-batch llh terms

__device__ __forceinline__ float fsigm(float x){ return 1.f/(1.f+__expf(-x)); }
__device__ __forceinline__ float ftanh(float x){
    float ax=fabsf(x);
    float t=__expf(-2.f*ax);
    float r=(1.f-t)/(1.f+t);
    return copysignf(r,x);
}

// ---- packed fp32x2 helpers (sm_103a FFMA2 path) ----
__device__ __forceinline__ unsigned long long pk2(float lo, float hi){
    unsigned long long r;
    asm("mov.b64 %0, {%1,%2};" : "=l"(r) : "f"(lo), "f"(hi));
    return r;
}
__device__ __forceinline__ void ffma2(unsigned long long& d,
                                      unsigned long long a, unsigned long long b){
    asm("fma.rn.f32x2 %0, %1, %2, %0;" : "+l"(d) : "l"(a), "l"(b));
}

__device__ __forceinline__ uint32_t smem_u32(const void* p){
    uint32_t a;
    asm("{ .reg .u64 t; cvta.to.shared.u64 t, %1; cvt.u32.u64 %0, t; }"
        : "=r"(a) : "l"(p));
    return a;
}
__device__ __forceinline__ void dsmem_st4(uint32_t local_addr, uint32_t rank, float4 v){
    uint32_t ra;
    asm volatile("mapa.shared::cluster.u32 %0, %1, %2;" : "=r"(ra) : "r"(local_addr), "r"(rank));
    asm volatile("st.shared::cluster.v4.f32 [%0], {%1,%2,%3,%4};"
        :: "r"(ra), "f"(v.x), "f"(v.y), "f"(v.z), "f"(v.w) : "memory");
}
__device__ __forceinline__ void mbar_arrive_peer(uint32_t mb_local, uint32_t rank){
    asm volatile(
        "{\n\t"
        ".reg .b32 ra;\n\t"
        "mapa.shared::cluster.u32 ra, %0, %1;\n\t"
        "mbarrier.arrive.shared::cluster.b64 _, [ra];\n\t"
        "}"
        :: "r"(mb_local), "r"(rank) : "memory");
}
__device__ __forceinline__ void mbar_wait_cluster(uint32_t mb, uint32_t parity){
    asm volatile(
        "{\n\t"
        ".reg .pred P;\n\t"
        "WL_%=:\n\t"
        "mbarrier.try_wait.parity.acquire.cluster.shared::cta.b64 P, [%0], %1, 0x989680;\n\t"
        "@P bra.uni WD_%=;\n\t"
        "bra.uni WL_%=;\n\t"
        "WD_%=:\n\t"
        "}"
        :: "r"(mb), "r"(parity) : "memory");
}

// ---------------- K1: fused embed + gx GEMM (8192 x 2400 x 300) --------------
__global__ void __launch_bounds__(256) k_gx(
        const int* __restrict__ x, const float* __restrict__ emb,
        const float* __restrict__ wf, const float* __restrict__ wb,
        const float* __restrict__ bif, const float* __restrict__ bhf,
        const float* __restrict__ bib, const float* __restrict__ bhb){
    __shared__ float As[8][132];
    __shared__ float Bs[8][128];
    int t  = threadIdx.x;
    int m0 = blockIdx.x*128;
    int n0 = blockIdx.y*128;
    int tx = t & 15, ty = t >> 4;

    unsigned long long acc2[8][4];
    #pragma unroll
    for (int i=0;i<8;i++)
        #pragma unroll
        for (int j=0;j<4;j++) acc2[i][j]=pk2(0.f,0.f);

    int arow = t>>1, ahalf = t&1;
    int bn = t>>1,  bh = t&1;
    int m_ = m0 + arow;
    int s_ = m_ >> 5, b_ = m_ & 31;
    const float* arowp = emb + (size_t)__ldg(&x[b_*Sx + s_])*EMBD;

    bool brow_ok = (n0+bn) < NCOL;
    const float* wrp = brow_ok
        ? ((n0+bn) < GATES ? wf + (size_t)(n0+bn)*EMBD
                           : wb + (size_t)(n0+bn-GATES)*EMBD)
        : wf;

    float4 aR, bRv;
    {
        aR  = *(const float4*)(arowp + ahalf*4);
        bRv = brow_ok ? *(const float4*)(wrp + bh*4)
                      : make_float4(0.f,0.f,0.f,0.f);
    }
    for (int ck=0; ck<38; ck++){
        __syncthreads();
        {   float av[4]={aR.x,aR.y,aR.z,aR.w};
            float bv[4]={bRv.x,bRv.y,bRv.z,bRv.w};
            #pragma unroll
            for (int i=0;i<4;i++){ As[ahalf*4+i][arow]=av[i]; Bs[bh*4+i][bn]=bv[i]; }
        }
        __syncthreads();
        if (ck < 37){
            int k0=(ck+1)*8;
            int ka = k0 + ahalf*4;
            int kb = k0 + bh*4;
            aR = (ka<EMBD) ? *(const float4*)(arowp + ka)
                           : make_float4(0.f,0.f,0.f,0.f);
            bRv = (brow_ok && kb<EMBD) ? *(const float4*)(wrp + kb)
                                       : make_float4(0.f,0.f,0.f,0.f);
        }
        #pragma unroll
        for (int kk=0;kk<8;kk++){
            float4 a0=*(const float4*)&As[kk][ty*8];
            float4 a1=*(const float4*)&As[kk][ty*8+4];
            float av[8]={a0.x,a0.y,a0.z,a0.w,a1.x,a1.y,a1.z,a1.w};
            unsigned long long ad[8];
            #pragma unroll
            for (int i=0;i<8;i++) ad[i]=pk2(av[i],av[i]);
            ulonglong2 bq0 = *(const ulonglong2*)&Bs[kk][tx*8];
            ulonglong2 bq1 = *(const ulonglong2*)&Bs[kk][tx*8+4];
            unsigned long long bp[4]={bq0.x,bq0.y,bq1.x,bq1.y};
            #pragma unroll
            for (int i=0;i<8;i++)
                #pragma unroll
                for (int j=0;j<4;j++)
                    ffma2(acc2[i][j], ad[i], bp[j]);
        }
    }
    #pragma unroll
    for (int i=0;i<8;i++){
        int gm = m0 + ty*8 + i;
        float vv[8];
        #pragma unroll
        for (int j=0;j<4;j++){
            asm("mov.b64 {%0,%1}, %2;" : "=f"(vv[2*j]), "=f"(vv[2*j+1]) : "l"(acc2[i][j]));
        }
        #pragma unroll
        for (int j0=0;j0<8;j0+=4){
            int gn = n0 + tx*8 + j0;
            if (gn < NCOL){
                float ww[4];
                #pragma unroll
                for (int j=0;j<4;j++){
                    int c=gn+j;
                    float bias = (c<GATES)? bif[c]+bhf[c] : bib[c-GATES]+bhb[c-GATES];
                    ww[j]=vv[j0+j]+bias;
                }
                *(float4*)(g_gx + (size_t)gm*NCOL + gn) =
                    make_float4(ww[0],ww[1],ww[2],ww[3]);
            }
        }
    }
}

// ---------------- K2: cluster-parallel persistent BiLSTM recurrence ----------
// R11 base with PUSH-v2 h-exchange: cell -> smem staging -> bulk float4
// st.shared::cluster pushes to all 12 CTAs (in the post-cell slack window),
// so the next step's GEMM reads LOCAL smem with no post-wait gather.
#define HSC   25        // hidden units per CTA
#define NHSC  12        // CTAs per cluster (hidden slices)
#define NBSC  4         // batch slices (8 each)
#define BCH   8         // batch per CTA
#define NGC   100       // 4*HSC gate rows per CTA
#define KSP   12        // k chunks
#define KCH   25        // k per chunk
#define PROWC 10        // padded Part row stride (even -> 8B-aligned pair stores)
#define HS2_OFF  0                      // [2][300][8]  (4800 floats)
#define HNEW_OFF 4800                   // [200] staging for own h slice
#define PART_OFF 5000                   // [12][100][10]
#define CS_OFF   (PART_OFF + KSP*NGC*PROWC)
#define MB_OFF   (CS_OFF + 200)         // byte offset divisible by 8
#define RECUR_SMEM ((MB_OFF + 4)*4)

__global__ void __launch_bounds__(256,1) k_recur(
        const float* __restrict__ whhf, const float* __restrict__ whhb){
    extern __shared__ float sm[];
    float* Hs2  = sm + HS2_OFF;    // [2][300][8] full h(s-1), k-major x batch
    float* Hnew = sm + HNEW_OFF;   // [25*8] own new h slice (staging)
    float* Part = sm + PART_OFF;   // [12][100][10]
    float* Cs   = sm + CS_OFF;     // [25*8]

    int t = threadIdx.x;
    int cid  = blockIdx.x / NHSC;
    uint32_t rank = blockIdx.x % NHSC;
    int dir = cid >> 2;
    int bs  = cid & 3;
    int b0g = bs*BCH;
    int j0  = rank*HSC;
    const float* whh = dir ? whhb : whhf;

    bool comp = (t < 240);
    int kp = t/20, gt = t%20;

    float W[5][25];
    if (comp){
        #pragma unroll
        for (int rr=0;rr<5;rr++){
            int lr = gt*5+rr;
            int type = lr/HSC, jj = lr - type*HSC;
            const float* src = whh + (size_t)(type*HIDD + j0 + jj)*HIDD + kp*KCH;
            #pragma unroll
            for (int k=0;k<KCH;k++) W[rr][k]=src[k];
        }
    }
    for (int i=t;i<4800;i+=256) Hs2[i]=0.f;
    for (int i=t;i<200;i+=256){ Hnew[i]=0.f; Cs[i]=0.f; }

    uint32_t smb = smem_u32(sm);
    uint32_t mb  = smb + MB_OFF*4;
    if (t==0){
        asm volatile("mbarrier.init.shared.b64 [%0], %1;" :: "r"(mb), "r"(NHSC) : "memory");
    }
    __syncthreads();
    asm volatile("barrier.cluster.arrive.aligned;" ::: "memory");
    asm volatile("barrier.cluster.wait.aligned;"   ::: "memory");

    bool mycell = (t < 200);
    int cb = t/HSC, cj = t - cb*HSC;

    for (int step=0; step<Sx; step++){
        int s = dir ? (Sx-1-step) : step;
        int buf = step & 1;

        // prefetch gx (independent of peers -> issued before the wait)
        float pgi=0.f,pgf=0.f,pgg=0.f,pgo=0.f;
        if (mycell){
            const float* gp = g_gx + ((size_t)(s*Bx + b0g + cb))*NCOL + dir*GATES + (j0+cj);
            pgi=gp[0]; pgf=gp[HIDD]; pgg=gp[2*HIDD]; pgo=gp[3*HIDD];
        }

        // wait for peers' end-of-previous-step arrives; h(s-1) is ALREADY in
        // local Hs2[buf] (pushed by peers). acquire orders those stores.
        if (step>0) mbar_wait_cluster(mb, (uint32_t)((step-1)&1));

        // recurrent GEMM: 5 rows x 4 batch-pairs x 25 k per thread (f32x2)
        if (comp){
            unsigned long long acc[5][4];
            #pragma unroll
            for (int rr=0;rr<5;rr++)
                #pragma unroll
                for (int p=0;p<4;p++) acc[rr][p]=pk2(0.f,0.f);
            const float* hbase = Hs2 + buf*2400 + (kp*KCH)*8;
            #pragma unroll
            for (int c=0;c<KCH;c++){
                ulonglong2 hA = *(const ulonglong2*)(hbase + c*8);
                ulonglong2 hB = *(const ulonglong2*)(hbase + c*8 + 4);
                unsigned long long hp[4]={hA.x,hA.y,hB.x,hB.y};
                #pragma unroll
                for (int rr=0;rr<5;rr++){
                    unsigned long long wd = pk2(W[rr][c],W[rr][c]);
                    #pragma unroll
                    for (int p=0;p<4;p++) ffma2(acc[rr][p], wd, hp[p]);
                }
            }
            #pragma unroll
            for (int rr=0;rr<5;rr++){
                int row = gt*5+rr;
                #pragma unroll
                for (int p=0;p<4;p++)
                    *(unsigned long long*)&Part[(kp*NGC+row)*PROWC + 2*p] = acc[rr][p];
            }
        }
        __syncthreads();                                    // B (gemm -> cell)

        // cell update -> staging
        if (mycell){
            float gi=pgi, gf=pgf, gg=pgg, go=pgo;
            #pragma unroll
            for (int kq=0;kq<KSP;kq++){
                gi += Part[(kq*NGC + 0*HSC+cj)*PROWC + cb];
                gf += Part[(kq*NGC + 1*HSC+cj)*PROWC + cb];
                gg += Part[(kq*NGC + 2*HSC+cj)*PROWC + cb];
                go += Part[(kq*NGC + 3*HSC+cj)*PROWC + cb];
            }
            float co=Cs[cj*8+cb];
            float cn=fsigm(gf)*co + fsigm(gi)*ftanh(gg);
            float hn=fsigm(go)*ftanh(cn);
            Cs[cj*8+cb]=cn;
            Hnew[cj*8+cb]=hn;
            g_H[((size_t)(s*Bx + b0g + cb))*(2*HIDD) + dir*HIDD + j0 + cj]=hn;
        }
        __syncthreads();                                    // C (Hnew complete)

        // push own slice (contiguous 200 floats at Hs2[nbuf] + j0*8) to all
        // 12 cluster CTAs: 600 float4 remote stores over 256 threads.
        {
            int nbuf = (step+1)&1;
            uint32_t dstbase = (uint32_t)((HS2_OFF + nbuf*2400 + j0*8)*4);
            const float4* src4 = (const float4*)Hnew;
            for (int i=t;i<NHSC*50;i+=256){
                int dst = i/50, q = i-dst*50;
                dsmem_st4(smb + dstbase + (uint32_t)q*16, (uint32_t)dst, src4[q]);
            }
        }
        __syncthreads();                                    // D (pushes issued)
        if (t < NHSC) mbar_arrive_peer(mb, (uint32_t)t);
    }
    asm volatile("barrier.cluster.arrive.aligned;" ::: "memory");
    asm volatile("barrier.cluster.wait.aligned;"   ::: "memory");
}

// ---------------- K3a: logits + softmax + CRF numerator terms ----------------
__global__ void __launch_bounds__(288) k_head(
        const float* __restrict__ linw, const float* __restrict__ linb,
        const int* __restrict__ y, const float* __restrict__ start_t,
        const float* __restrict__ end_t, const float* __restrict__ trans,
        float* __restrict__ out){
    __shared__ float sh[2*HIDD];
    __shared__ float lg[NTAG];
    int bxid=blockIdx.x;
    int b=bxid/Sx, s=bxid%Sx;
    int t=threadIdx.x;
    const float* hrow=g_H + (size_t)(s*Bx+b)*(2*HIDD);
    for (int k=t;k<2*HIDD;k+=288) sh[k]=hrow[k];
    __syncthreads();
    int w=t>>5, lane=t&31;
    float acc=0.f;
    for (int k=lane;k<2*HIDD;k+=32) acc=fmaf(sh[k],__ldg(&linw[w*(2*HIDD)+k]),acc);
    #pragma unroll
    for (int off=16;off;off>>=1) acc += __shfl_down_sync(0xffffffffu,acc,off);
    if (lane==0) lg[w]=acc+__ldg(&linb[w]);
    __syncthreads();
    if (t==0){
        float m=lg[0];
        #pragma unroll
        for (int i=1;i<NTAG;i++) m=fmaxf(m,lg[i]);
        float e[NTAG]; float ssum=0.f;
        #pragma unroll
        for (int i=0;i<NTAG;i++){ e[i]=expf(lg[i]-m); ssum+=e[i]; }
        float inv=1.f/ssum;
        float* po=out + ((size_t)b*Sx + s)*NTAG;
        float pr[NTAG];
        #pragma unroll
        for (int i=0;i<NTAG;i++){ pr[i]=e[i]*inv; po[i]=pr[i]; }
        int yc=__ldg(&y[b*Sx+s]);
        float term=pr[yc];
        if (s==0) term += __ldg(&start_t[yc]);
        else      term += __ldg(&trans[__ldg(&y[b*Sx+s-1])*NTAG + yc]);
        if (s==Sx-1) term += __ldg(&end_t[yc]);
        g_sc[b*Sx+s]=term;
    }
}

// ---------------- K3b: CRF forward, linear domain + smem-staged emissions ----
__global__ void __launch_bounds__(32) k_crf(
        const float* __restrict__ start_t, const float* __restrict__ end_t,
        const float* __restrict__ trans, const float* __restrict__ out){
    __shared__ float sp[Sx*NTAG];
    __shared__ float ssc[Sx];
    int w = blockIdx.x;
    int lane = threadIdx.x;

    {
        const float4* src = (const float4*)(out + (size_t)w*Sx*NTAG);
        for (int i=lane;i<(Sx*NTAG)/4;i+=32) ((float4*)sp)[i]=src[i];
        const float4* ssrc = (const float4*)(g_sc + w*Sx);
        for (int i=lane;i<Sx/4;i+=32) ((float4*)ssc)[i]=ssrc[i];
    }
    __syncwarp();

    int j = (lane<NTAG)? lane : 0;
    float M[NTAG];
    #pragma unroll
    for (int i=0;i<NTAG;i++) M[i]=__expf(__ldg(&trans[i*NTAG+j]));

    float A = __expf(__ldg(&start_t[j]) + sp[j]);
    float off = 0.f;
    for (int s=1;s<Sx;s++){
        float em = sp[s*NTAG+j];
        float a[NTAG];
        #pragma unroll
        for (int i=0;i<NTAG;i++) a[i]=__shfl_sync(0xffffffffu, A, i);
        float S0=0.f, S1=0.f, S2=0.f;
        #pragma unroll
        for (int i=0;i<NTAG;i+=3){
            S0=fmaf(M[i  ],a[i  ],S0);
            S1=fmaf(M[i+1],a[i+1],S1);
            S2=fmaf(M[i+2],a[i+2],S2);
        }
        A = (S0+S1+S2) * __expf(em);
        if ((s&15)==0){
            float tot=0.f;
            #pragma unroll
            for (int i=0;i<NTAG;i++) tot += __shfl_sync(0xffffffffu, A, i);
            A = A / tot;
            off += __logf(tot);
        }
    }
    float v = A * __expf(__ldg(&end_t[j]));
    float dl=0.f;
    #pragma unroll
    for (int i=0;i<NTAG;i++) dl += __shfl_sync(0xffffffffu, v, i);
    float denom = __logf(dl) + off;
    float sc=0.f;
    for (int s=lane;s<Sx;s+=32) sc+=ssc[s];
    #pragma unroll
    for (int o=16;o;o>>=1) sc += __shfl_down_sync(0xffffffffu,sc,o);
    if (lane==0) g_res[w]=sc-denom;
}

// ---------------- K3c: final deterministic loss sum ----------------
__global__ void __launch_bounds__(32) k_loss(float* __restrict__ out){
    if (threadIdx.x==0){
        float llh=0.f;
        #pragma unroll
        for (int bb=0;bb<Bx;bb++) llh+=g_res[bb];
        out[(size_t)Bx*Sx*NTAG]=-llh;
    }
}

// ---------------- launcher ----------------
extern "C" void kernel_launch(void* const* d_in, const int* in_sizes, int n_in,
                              void* d_out, int out_size){
    const int*   x     =(const int*)  d_in[0];
    const int*   y     =(const int*)  d_in[1];
    const float* emb   =(const float*)d_in[2];
    const float* wihf  =(const float*)d_in[3];
    const float* whhf  =(const float*)d_in[4];
    const float* bihf  =(const float*)d_in[5];
    const float* bhhf  =(const float*)d_in[6];
    const float* wihb  =(const float*)d_in[7];
    const float* whhb  =(const float*)d_in[8];
    const float* bihb  =(const float*)d_in[9];
    const float* bhhb  =(const float*)d_in[10];
    const float* linw  =(const float*)d_in[11];
    const float* linb  =(const float*)d_in[12];
    const float* startt=(const float*)d_in[13];
    const float* endt  =(const float*)d_in[14];
    const float* trans =(const float*)d_in[15];
    float* out=(float*)d_out;
    (void)in_sizes; (void)n_in; (void)out_size;

    static int once = 0;
    if (!once){
        cudaFuncSetAttribute(k_recur, cudaFuncAttributeMaxDynamicSharedMemorySize, RECUR_SMEM);
        cudaFuncSetAttribute(k_recur, cudaFuncAttributeNonPortableClusterSizeAllowed, 1);
        once = 1;
    }

    dim3 gg(8192/128, (NCOL+127)/128);
    k_gx<<<gg,256>>>(x, emb, wihf, wihb, bihf, bhhf, bihb, bhhb);

    cudaLaunchConfig_t cfg = {};
    cfg.gridDim = dim3(2*NBSC*NHSC, 1, 1);   // 96 CTAs = 8 clusters x 12
    cfg.blockDim = dim3(256, 1, 1);
    cfg.dynamicSmemBytes = RECUR_SMEM;
    cfg.stream = 0;
    cudaLaunchAttribute attrs[1];
    attrs[0].id = cudaLaunchAttributeClusterDimension;
    attrs[0].val.clusterDim.x = NHSC;
    attrs[0].val.clusterDim.y = 1;
    attrs[0].val.clusterDim.z = 1;
    cfg.attrs = attrs;
    cfg.numAttrs = 1;
    cudaLaunchKernelEx(&cfg, k_recur, whhf, whhb);

    k_head<<<Bx*Sx,288>>>(linw, linb, y, startt, endt, trans, out);
    k_crf<<<Bx,32>>>(startt, endt, trans, out);
    k_loss<<<1,32>>>(out);
}